// round 17
// baseline (speedup 1.0000x reference)
#include <cuda_runtime.h>
#include <math.h>
#include <stdint.h>

#define NUM_NODES 17185
#define D 6
#define FEATS (NUM_NODES * D)               // 103110
#define BATCH 256
#define NPB 32                              // nodes per block
#define NBLK ((NUM_NODES + NPB - 1) / NPB)  // 538
#define RPS 16                              // rows per stage
#define NSTAGE (BATCH / RPS)                // 16
#define F4PR 49                             // float4 per staged row (784 B)
#define STAGE_F4 (RPS * F4PR)               // 784
#define EPS 1e-5f

__device__ float g_partial[NBLK * BATCH];   // [blk][b]
__device__ unsigned int g_ctr = 0;          // self-resetting arrival counter

__global__ __launch_bounds__(256, 2)
void fused_kernel(const float* __restrict__ data,
                  const float* __restrict__ w_blocks,
                  const float* __restrict__ b_blocks,
                  const float* __restrict__ bn_gamma,
                  const float* __restrict__ bn_beta,
                  const float* __restrict__ bn_mean,
                  const float* __restrict__ bn_var,
                  const float* __restrict__ fc_w,
                  const float* __restrict__ fc_b,
                  const float* __restrict__ bnf_gamma,
                  const float* __restrict__ bnf_beta,
                  const float* __restrict__ bnf_mean,
                  const float* __restrict__ bnf_var,
                  float* __restrict__ out)
{
    __shared__ float4 sBuf[2][STAGE_F4];    // 2 x 12.5 KB stage double buffer
    __shared__ float  sW[NPB * 36];         // 4.5 KB staged weights
    __shared__ float  sP[6][NPB * D];       // staged params (zero-filled OOB)
    __shared__ unsigned int s_last;

    const int tid   = threadIdx.x;
    const int lane  = tid & 31;             // node lane: node = node0 + lane
    const int warp  = tid >> 5;             // 0..7 -> rows warp, warp+8 per stage
    const int node0 = blockIdx.x * NPB;

    const char*  dbytes = (const char*)data;
    const size_t FEATSB = (size_t)FEATS * 4;           // == 8 (mod 16)
    const size_t TOTALB = (size_t)BATCH * FEATSB;
    const size_t SSTEP  = (size_t)RPS * FEATSB;        // stage stride in bytes

    // ---- per-thread canonical-stream descriptors (stage-invariant) ----
    // Stage rows are contiguous 768B gmem slices; aligned down 8B on odd rows.
    size_t ga[4];  int sj[4];  bool en[4];
    #pragma unroll
    for (int k = 0; k < 4; ++k) {
        const int j = tid + k * 256;
        en[k] = (j < STAGE_F4);
        sj[k] = en[k] ? j : 0;
        const int row = sj[k] / F4PR;
        const int v   = sj[k] % F4PR;
        size_t base = (size_t)row * FEATSB + (size_t)node0 * 24;
        base -= (size_t)((row & 1) * 8);               // 16B align-down
        ga[k] = base + (size_t)v * 16;
    }

    float4 rbuf[4];
    auto ldg_stage = [&](int s) {
        const size_t so = (size_t)s * SSTEP;
        #pragma unroll
        for (int k = 0; k < 4; ++k) {
            const size_t a = ga[k] + so;
            if (en[k] && a + 16 <= TOTALB)
                rbuf[k] = *reinterpret_cast<const float4*>(dbytes + a);
            else
                rbuf[k] = make_float4(0.f, 0.f, 0.f, 0.f);
        }
    };
    auto sts_stage = [&](int buf) {
        #pragma unroll
        for (int k = 0; k < 4; ++k)
            if (en[k]) sBuf[buf][sj[k]] = rbuf[k];
    };

    // ---- prologue: stage 0+1 in flight, weights/params staged coalesced ----
    ldg_stage(0);
    for (int i = tid; i < NPB * 36; i += 256) {
        const int gi = node0 * 36 + i;
        sW[i] = (gi < NUM_NODES * 36) ? w_blocks[gi] : 0.0f;
    }
    for (int i = tid; i < 6 * NPB * D; i += 256) {
        const int a = i / (NPB * D), j = i % (NPB * D);
        const int gi = node0 * D + j;
        const float* src = (a == 0) ? b_blocks : (a == 1) ? bn_gamma :
                           (a == 2) ? bn_beta  : (a == 3) ? bn_mean  :
                           (a == 4) ? bn_var   : fc_w;
        sP[a][i % (NPB * D)] = (gi < FEATS) ? src[gi] : 0.0f;
    }
    sts_stage(0);
    ldg_stage(1);
    __syncthreads();

    // Per-thread node state from smem (zero-filled => invalid nodes give 0).
    float W[36], bias[D], A[D];
    float CN = 0.0f;
    #pragma unroll
    for (int k = 0; k < 36; ++k) W[k] = sW[lane * 36 + k];
    #pragma unroll
    for (int o = 0; o < D; ++o) {
        const int j = lane * D + o;
        bias[o] = sP[0][j];
        const float rs = rsqrtf(sP[4][j] + EPS);
        const float g  = sP[1][j] * rs;
        const float fw = sP[5][j];
        A[o]  = g * fw;                     // 0 for invalid nodes
        CN   += (sP[2][j] - sP[3][j] * g) * fw;
    }

    // ---- mainloop: 16 stages; LDGs for s+2 outstanding through compute(s) ----
    float keep = 0.0f;
    #pragma unroll 1
    for (int s = 0; s < NSTAGE; ++s) {
        const int cur = s & 1;
        if (s + 1 < NSTAGE) sts_stage(1 - cur);   // stage s+1 regs -> smem
        if (s + 2 < NSTAGE) ldg_stage(s + 2);     // deep loads in flight NOW

        #pragma unroll
        for (int r = 0; r < 2; ++r) {
            const int row = warp + r * 8;         // this warp's row in stage
            const float* rp = reinterpret_cast<const float*>(&sBuf[cur][row * F4PR])
                              + ((row & 1) ? 2 : 0) + lane * 6;
            const float2 x01 = *reinterpret_cast<const float2*>(rp + 0);
            const float2 x23 = *reinterpret_cast<const float2*>(rp + 2);
            const float2 x45 = *reinterpret_cast<const float2*>(rp + 4);
            const float x[D] = {x01.x, x01.y, x23.x, x23.y, x45.x, x45.y};
            float acc = CN;
            #pragma unroll
            for (int o = 0; o < D; ++o) {
                float t = bias[o];
                #pragma unroll
                for (int i = 0; i < D; ++i)
                    t = fmaf(x[i], W[o * D + i], t);
                t = fmaxf(t, 0.0f);               // ReLU
                acc = fmaf(t, A[o], acc);         // folded BN * fc_w
            }
            // Butterfly over 32 node lanes (fixed order -> deterministic).
            #pragma unroll
            for (int off = 16; off > 0; off >>= 1)
                acc += __shfl_xor_sync(0xffffffffu, acc, off);
            if (lane == s * 2 + r) keep = acc;    // slot (s,r) -> lane
        }
        __syncthreads();                          // stage consumed / STS visible
    }

    // lane l holds row b = (l>>1)*16 + (l&1)*8 + warp
    g_partial[blockIdx.x * BATCH + ((lane >> 1) * 16 + (lane & 1) * 8 + warp)] = keep;

    // ---- last-block tail (deterministic fixed-order reduction) ----
    __syncthreads();
    if (tid == 0) {
        __threadfence();                          // release
        const unsigned int old = atomicAdd(&g_ctr, 1u);
        s_last = (old == (unsigned)(NBLK - 1)) ? 1u : 0u;
        if (s_last) atomicExch(&g_ctr, 0u);       // reset for next launch
    }
    __syncthreads();
    if (!s_last) return;
    if (tid == 0) __threadfence();                // acquire
    __syncthreads();

    {
        const int b = tid;                        // 256 threads = 256 rows
        float s0 = 0.f, s1 = 0.f, s2 = 0.f, s3 = 0.f;
        int k = 0;
        for (; k + 4 <= NBLK; k += 4) {           // fixed grouping
            s0 += g_partial[(k + 0) * BATCH + b]; // coalesced across b
            s1 += g_partial[(k + 1) * BATCH + b];
            s2 += g_partial[(k + 2) * BATCH + b];
            s3 += g_partial[(k + 3) * BATCH + b];
        }
        for (; k < NBLK; ++k) s0 += g_partial[k * BATCH + b];
        const float t  = ((s0 + s1) + (s2 + s3)) + fc_b[0];
        const float rs = rsqrtf(bnf_var[0] + EPS);
        const float y  = (t - bnf_mean[0]) * rs * bnf_gamma[0] + bnf_beta[0];
        out[b] = 1.0f / (1.0f + expf(-y));
    }
}

extern "C" void kernel_launch(void* const* d_in, const int* in_sizes, int n_in,
                              void* d_out, int out_size) {
    const float* data      = (const float*)d_in[0];
    const float* w_blocks  = (const float*)d_in[1];
    const float* b_blocks  = (const float*)d_in[2];
    const float* bn_gamma  = (const float*)d_in[3];
    const float* bn_beta   = (const float*)d_in[4];
    const float* bn_mean   = (const float*)d_in[5];
    const float* bn_var    = (const float*)d_in[6];
    const float* fc_w      = (const float*)d_in[7];
    const float* fc_b      = (const float*)d_in[8];
    const float* bnf_gamma = (const float*)d_in[9];
    const float* bnf_beta  = (const float*)d_in[10];
    const float* bnf_mean  = (const float*)d_in[11];
    const float* bnf_var   = (const float*)d_in[12];
    float* out = (float*)d_out;

    fused_kernel<<<NBLK, 256>>>(data, w_blocks, b_blocks, bn_gamma, bn_beta,
                                bn_mean, bn_var, fc_w, fc_b, bnf_gamma,
                                bnf_beta, bnf_mean, bnf_var, out);
}